// round 6
// baseline (speedup 1.0000x reference)
#include <cuda_runtime.h>
#include <math.h>

// Problem constants
#define NB      8192      // batch
#define ND      32        // dims
#define NK      64        // mixture components
#define NSTEP   255       // Euler-Maruyama steps (N_ITER - 1)
#define TPB     224       // 7 warps: 28 groups of 8 threads
#define GSIZE   8         // threads per group (K split); each group does 2 samples
#define KPER    (NK / GSIZE)   // 8 components per thread
#define STRIDE  36        // smem row stride in floats (144B, 16B aligned, conflict-free)
#define NBLK    148       // one block per SM
// 52 blocks x 56 samples + 96 blocks x 55 samples = 8192

__global__ __launch_bounds__(TPB, 1)
void sbm_kernel(const float* __restrict__ x_init,
                const float* __restrict__ centers,
                const float* __restrict__ stds,
                const float* __restrict__ weights,
                const float* __restrict__ noise,
                float* __restrict__ out)
{
    __shared__ float sm_nm[NK * STRIDE];   // NEGATED diffused means
    __shared__ float sm_iv[NK * STRIDE];   // inverse diffused variances
    __shared__ float sm_c [NK];            // per-component log constant

    const int tid   = threadIdx.x;
    const int kpart = tid & (GSIZE - 1);   // 0..7
    const int g     = tid >> 3;            // group 0..27

    const int b    = blockIdx.x;
    const int cnt  = (b < 52) ? 56 : 55;
    const int base = 55 * b + min(b, 52);

    // two samples per thread; slot 2g always valid (2*27=54 < 55), slot 2g+1 may clamp
    const int  s0 = base + 2 * g;
    const bool v1 = (2 * g + 1) < cnt;
    const int  s1 = base + min(2 * g + 1, cnt - 1);

    float x0[ND], x1[ND];
    {
        const float4* p0 = reinterpret_cast<const float4*>(x_init + (size_t)s0 * ND);
        const float4* p1 = reinterpret_cast<const float4*>(x_init + (size_t)s1 * ND);
        #pragma unroll
        for (int j = 0; j < 8; j++) {
            float4 a = p0[j], c = p1[j];
            x0[4*j+0]=a.x; x0[4*j+1]=a.y; x0[4*j+2]=a.z; x0[4*j+3]=a.w;
            x1[4*j+0]=c.x; x1[4*j+1]=c.y; x1[4*j+2]=c.z; x1[4*j+3]=c.w;
        }
    }

    const float T_MAX = 1.0f;
    const float T_MIN = 1e-4f;
    const float H   = (T_MAX - T_MIN) / 255.0f;
    const float SQH = sqrtf(H);

    for (int i = 0; i < NSTEP; i++) {
        float t  = T_MAX - (float)i * H;
        float bt = 0.1f + 19.9f * t;                 // beta(t)
        float Bt = 0.1f * t + 9.95f * t * t;         // Beta(t)
        float eB = expf(-Bt);
        float om = 1.0f - eB;
        float sq = sqrtf(eB);
        float hb = H * bt;                           // -dt * beta (positive)
        float sn = sqrtf(bt) * SQH;

        __syncthreads();   // previous step's table readers are done

        // ---- build per-step mixture table (threads 0..127 = warps 0-3) ----
        if (tid < 128) {
            int k = tid >> 1;
            int h = (tid & 1) * 16;                  // dim half: 0 or 16
            float lsum = 0.0f;
            #pragma unroll
            for (int jj = 0; jj < 4; jj++) {
                int d = h + jj * 4;
                float4 c4 = *reinterpret_cast<const float4*>(centers + k * ND + d);
                float4 s4 = *reinterpret_cast<const float4*>(stds    + k * ND + d);
                float v0 = eB * s4.x * s4.x + om;
                float v1v= eB * s4.y * s4.y + om;
                float v2 = eB * s4.z * s4.z + om;
                float v3 = eB * s4.w * s4.w + om;
                float4 nm4 = make_float4(-(sq*c4.x), -(sq*c4.y), -(sq*c4.z), -(sq*c4.w));
                float4 iv4 = make_float4(1.0f/v0, 1.0f/v1v, 1.0f/v2, 1.0f/v3);
                *reinterpret_cast<float4*>(sm_nm + k * STRIDE + d) = nm4;
                *reinterpret_cast<float4*>(sm_iv + k * STRIDE + d) = iv4;
                const float TWO_PI = 6.2831853071795864f;
                lsum += __logf(TWO_PI*v0) + __logf(TWO_PI*v1v)
                      + __logf(TWO_PI*v2) + __logf(TWO_PI*v3);
            }
            lsum += __shfl_xor_sync(0xffffffffu, lsum, 1);
            if ((tid & 1) == 0) {
                // reference: -(0.5*D) * sum(log(2*pi*v)) + log(w),  D = 32
                sm_c[k] = fmaf(-16.0f, lsum, __logf(weights[k]));
            }
        }
        __syncthreads();

        // ---- online softmax over this thread's 8 components, 2 samples ----
        float M0 = -INFINITY, S0 = 0.0f;
        float M1 = -INFINITY, S1 = 0.0f;
        float acc0[ND], acc1[ND];
        float dv0 [ND], dv1 [ND];
        #pragma unroll
        for (int d = 0; d < ND; d++) { acc0[d] = 0.0f; acc1[d] = 0.0f; }

        #pragma unroll 1
        for (int kk = 0; kk < KPER; kk++) {
            int k = kk * GSIZE + kpart;   // lanes 0..7 of a group take consecutive k
            const float4* nmp = reinterpret_cast<const float4*>(sm_nm + k * STRIDE);
            const float4* ivp = reinterpret_cast<const float4*>(sm_iv + k * STRIDE);

            float sa0 = 0.f, sb0 = 0.f, sa1 = 0.f, sb1 = 0.f;
            #pragma unroll
            for (int j = 0; j < 8; j++) {
                float4 m  = nmp[j];
                float4 iv = ivp[j];
                int d = 4 * j;
                // sample 0
                {
                    float a0 = x0[d+0] + m.x;
                    float a1 = x0[d+1] + m.y;
                    float a2 = x0[d+2] + m.z;
                    float a3 = x0[d+3] + m.w;
                    float b0 = a0 * iv.x;
                    float b1 = a1 * iv.y;
                    float b2 = a2 * iv.z;
                    float b3 = a3 * iv.w;
                    sa0 = fmaf(b0, a0, sa0);
                    sb0 = fmaf(b1, a1, sb0);
                    sa0 = fmaf(b2, a2, sa0);
                    sb0 = fmaf(b3, a3, sb0);
                    dv0[d+0] = b0; dv0[d+1] = b1; dv0[d+2] = b2; dv0[d+3] = b3;
                }
                // sample 1
                {
                    float a0 = x1[d+0] + m.x;
                    float a1 = x1[d+1] + m.y;
                    float a2 = x1[d+2] + m.z;
                    float a3 = x1[d+3] + m.w;
                    float b0 = a0 * iv.x;
                    float b1 = a1 * iv.y;
                    float b2 = a2 * iv.z;
                    float b3 = a3 * iv.w;
                    sa1 = fmaf(b0, a0, sa1);
                    sb1 = fmaf(b1, a1, sb1);
                    sa1 = fmaf(b2, a2, sa1);
                    sb1 = fmaf(b3, a3, sb1);
                    dv1[d+0] = b0; dv1[d+1] = b1; dv1[d+2] = b2; dv1[d+3] = b3;
                }
            }
            float cK = sm_c[k];
            float logc0 = fmaf(-0.5f, sa0 + sb0, cK);
            float logc1 = fmaf(-0.5f, sa1 + sb1, cK);

            // sample 0 online-softmax update
            if (logc0 > M0) {
                float r = __expf(M0 - logc0);        // exp(-inf)=0 handles first k
                S0 = fmaf(S0, r, 1.0f);
                #pragma unroll
                for (int d = 0; d < ND; d++) acc0[d] = fmaf(acc0[d], r, dv0[d]);
                M0 = logc0;
            } else {
                float w = __expf(logc0 - M0);
                S0 += w;
                #pragma unroll
                for (int d = 0; d < ND; d++) acc0[d] = fmaf(w, dv0[d], acc0[d]);
            }
            // sample 1 online-softmax update
            if (logc1 > M1) {
                float r = __expf(M1 - logc1);
                S1 = fmaf(S1, r, 1.0f);
                #pragma unroll
                for (int d = 0; d < ND; d++) acc1[d] = fmaf(acc1[d], r, dv1[d]);
                M1 = logc1;
            } else {
                float w = __expf(logc1 - M1);
                S1 += w;
                #pragma unroll
                for (int d = 0; d < ND; d++) acc1[d] = fmaf(w, dv1[d], acc1[d]);
            }
        }

        // ---- merge 8 partial softmax states (xor 1, 2, 4) ----
        #pragma unroll
        for (int r = 1; r <= 4; r <<= 1) {
            // sample 0
            {
                float Mo = __shfl_xor_sync(0xffffffffu, M0, r);
                float So = __shfl_xor_sync(0xffffffffu, S0, r);
                float Mn = fmaxf(M0, Mo);
                float es = __expf(M0 - Mn);
                float eo = __expf(Mo - Mn);
                S0 = S0 * es + So * eo;
                #pragma unroll
                for (int d = 0; d < ND; d++) {
                    float ao = __shfl_xor_sync(0xffffffffu, acc0[d], r);
                    acc0[d] = acc0[d] * es + ao * eo;
                }
                M0 = Mn;
            }
            // sample 1
            {
                float Mo = __shfl_xor_sync(0xffffffffu, M1, r);
                float So = __shfl_xor_sync(0xffffffffu, S1, r);
                float Mn = fmaxf(M1, Mo);
                float es = __expf(M1 - Mn);
                float eo = __expf(Mo - Mn);
                S1 = S1 * es + So * eo;
                #pragma unroll
                for (int d = 0; d < ND; d++) {
                    float ao = __shfl_xor_sync(0xffffffffu, acc1[d], r);
                    acc1[d] = acc1[d] * es + ao * eo;
                }
                M1 = Mn;
            }
        }

        // ---- Euler-Maruyama update, both samples ----
        float i0 = 1.0f / S0;
        float i1 = 1.0f / S1;
        const float4* n0 = reinterpret_cast<const float4*>(
            noise + ((size_t)i * NB + (size_t)s0) * ND);
        const float4* n1 = reinterpret_cast<const float4*>(
            noise + ((size_t)i * NB + (size_t)s1) * ND);
        #pragma unroll
        for (int j = 0; j < 8; j++) {
            float4 z0 = n0[j];
            float4 z1 = n1[j];
            int d = 4 * j;
            // c = 0.5*x - invS*acc ;  x += hb*c + sn*z
            float c0 = fmaf(-i0, acc0[d+0], 0.5f * x0[d+0]);
            float c1 = fmaf(-i0, acc0[d+1], 0.5f * x0[d+1]);
            float c2 = fmaf(-i0, acc0[d+2], 0.5f * x0[d+2]);
            float c3 = fmaf(-i0, acc0[d+3], 0.5f * x0[d+3]);
            x0[d+0] = fmaf(sn, z0.x, fmaf(hb, c0, x0[d+0]));
            x0[d+1] = fmaf(sn, z0.y, fmaf(hb, c1, x0[d+1]));
            x0[d+2] = fmaf(sn, z0.z, fmaf(hb, c2, x0[d+2]));
            x0[d+3] = fmaf(sn, z0.w, fmaf(hb, c3, x0[d+3]));

            float e0 = fmaf(-i1, acc1[d+0], 0.5f * x1[d+0]);
            float e1 = fmaf(-i1, acc1[d+1], 0.5f * x1[d+1]);
            float e2 = fmaf(-i1, acc1[d+2], 0.5f * x1[d+2]);
            float e3 = fmaf(-i1, acc1[d+3], 0.5f * x1[d+3]);
            x1[d+0] = fmaf(sn, z1.x, fmaf(hb, e0, x1[d+0]));
            x1[d+1] = fmaf(sn, z1.y, fmaf(hb, e1, x1[d+1]));
            x1[d+2] = fmaf(sn, z1.z, fmaf(hb, e2, x1[d+2]));
            x1[d+3] = fmaf(sn, z1.w, fmaf(hb, e3, x1[d+3]));
        }
    }

    // ---- write final x (lane 0 of each group writes its sample pair) ----
    if (kpart == 0) {
        float4* o0 = reinterpret_cast<float4*>(out + (size_t)s0 * ND);
        #pragma unroll
        for (int j = 0; j < 8; j++)
            o0[j] = make_float4(x0[4*j+0], x0[4*j+1], x0[4*j+2], x0[4*j+3]);
        if (v1) {
            float4* o1 = reinterpret_cast<float4*>(out + (size_t)s1 * ND);
            #pragma unroll
            for (int j = 0; j < 8; j++)
                o1[j] = make_float4(x1[4*j+0], x1[4*j+1], x1[4*j+2], x1[4*j+3]);
        }
    }
}

extern "C" void kernel_launch(void* const* d_in, const int* in_sizes, int n_in,
                              void* d_out, int out_size)
{
    const float* x_init  = (const float*)d_in[0];
    const float* centers = (const float*)d_in[1];
    const float* stds    = (const float*)d_in[2];
    const float* weights = (const float*)d_in[3];
    const float* noise   = (const float*)d_in[4];
    float* out = (float*)d_out;

    sbm_kernel<<<NBLK, TPB>>>(x_init, centers, stds, weights, noise, out);
}

// round 7
// speedup vs baseline: 1.0569x; 1.0569x over previous
#include <cuda_runtime.h>
#include <math.h>

// Problem constants
#define NB      8192
#define ND      32
#define NK      64
#define NSTEP   255
#define TPB     224      // 7 warps
#define GSIZE   16       // lanes per sample-pair group (half warp)
#define KPER    4        // 64 / 16 components per lane in pass 1
#define PAIRS   14       // groups per block
#define SPB     28       // samples per block
#define NBLK    296      // 2 blocks per SM x 148 SMs; 296*28 = 8288 slots >= 8192
#define TS4     17       // table row stride in float4 (odd -> bank spread)

typedef unsigned long long u64;

__device__ __forceinline__ void upk2(u64 v, float& lo, float& hi) {
    asm("mov.b64 {%0, %1}, %2;" : "=f"(lo), "=f"(hi) : "l"(v));
}
__device__ __forceinline__ u64 add2(u64 a, u64 b) {
    u64 d; asm("add.rn.f32x2 %0, %1, %2;" : "=l"(d) : "l"(a), "l"(b)); return d;
}
__device__ __forceinline__ u64 fma2_(u64 a, u64 b, u64 c) {
    u64 d; asm("fma.rn.f32x2 %0, %1, %2, %3;" : "=l"(d) : "l"(a), "l"(b), "l"(c)); return d;
}

__device__ __forceinline__ float upd1(float x, float P, float Q,
                                      float invS, float hb, float sn, float z) {
    // acc = -2xP - Q ;  c = 0.5x - invS*acc = 0.5x + invS*(2xP + Q)
    float tx = x + x;
    float u  = fmaf(tx, P, Q);
    float c  = fmaf(invS, u, 0.5f * x);
    return fmaf(sn, z, fmaf(hb, c, x));
}

__global__ __launch_bounds__(TPB, 2)
void sbm_kernel(const float* __restrict__ x_init,
                const float* __restrict__ centers,
                const float* __restrict__ stds,
                const float* __restrict__ weights,
                const float* __restrict__ noise,
                float* __restrict__ out)
{
    // table: per (k, dim-pair c): float4 { ivh[2c], ivh[2c+1], am[2c], am[2c+1] }
    //        ivh = -0.5/v,  am = m/v   (m = diffused mean)
    __shared__ float4 sm_tab[NK * TS4];
    __shared__ float  sm_c  [NK];
    __shared__ float4 sm_w  [PAIRS * NK];      // { w0, w0, w1, w1 } per (group, k)
    __shared__ float  sm_x  [PAIRS * 2 * ND];  // authoritative per-sample x

    const int tid  = threadIdx.x;
    const int lane = tid & (GSIZE - 1);        // 0..15
    const int grp  = tid >> 4;                 // 0..13
    const int d0   = lane * 2;                 // this lane's dim pair

    const int s0r = blockIdx.x * SPB + 2 * grp;
    const int s1r = s0r + 1;
    const int cs0 = min(s0r, NB - 1);
    const int cs1 = min(s1r, NB - 1);

    float* xs0 = sm_x + (grp * 2 + 0) * ND;
    float* xs1 = sm_x + (grp * 2 + 1) * ND;

    // init x-slab (each lane owns its 2 dims of both samples)
    *reinterpret_cast<float2*>(xs0 + d0) =
        *reinterpret_cast<const float2*>(x_init + (size_t)cs0 * ND + d0);
    *reinterpret_cast<float2*>(xs1 + d0) =
        *reinterpret_cast<const float2*>(x_init + (size_t)cs1 * ND + d0);

    const float T_MAX = 1.0f;
    const float T_MIN = 1e-4f;
    const float H   = (T_MAX - T_MIN) / 255.0f;
    const float SQH = sqrtf(H);

    float4* wrow = sm_w + grp * NK;

    for (int i = 0; i < NSTEP; i++) {
        float t  = T_MAX - (float)i * H;
        float bt = 0.1f + 19.9f * t;                 // beta(t)
        float Bt = 0.1f * t + 9.95f * t * t;         // Beta(t)
        float eB = expf(-Bt);
        float om = 1.0f - eB;
        float sq = sqrtf(eB);
        float hb = H * bt;
        float sn = sqrtf(bt) * SQH;

        __syncthreads();   // prior step's table readers done; x-slab STS visible

        // ---- build per-step table (threads 0..127: k = tid/2, half of dims) ----
        if (tid < 128) {
            int k = tid >> 1;
            int h = (tid & 1) * 16;
            float lsum = 0.0f, qsum = 0.0f;
            #pragma unroll
            for (int jj = 0; jj < 4; jj++) {
                int d = h + jj * 4;
                float4 c4 = *reinterpret_cast<const float4*>(centers + k * ND + d);
                float4 s4 = *reinterpret_cast<const float4*>(stds    + k * ND + d);
                float v0 = eB * s4.x * s4.x + om;
                float v1 = eB * s4.y * s4.y + om;
                float v2 = eB * s4.z * s4.z + om;
                float v3 = eB * s4.w * s4.w + om;
                float i0 = 1.0f / v0, i1 = 1.0f / v1, i2 = 1.0f / v2, i3 = 1.0f / v3;
                float m0 = sq * c4.x, m1 = sq * c4.y, m2 = sq * c4.z, m3 = sq * c4.w;
                float a0 = m0 * i0, a1 = m1 * i1, a2 = m2 * i2, a3 = m3 * i3;
                // chunks: {ivh, ivh, am, am} per dim-pair
                sm_tab[k * TS4 + (d >> 1)    ] = make_float4(-0.5f*i0, -0.5f*i1, a0, a1);
                sm_tab[k * TS4 + (d >> 1) + 1] = make_float4(-0.5f*i2, -0.5f*i3, a2, a3);
                qsum += a0*m0 + a1*m1 + a2*m2 + a3*m3;     // sum m^2/v
                const float TWO_PI = 6.2831853071795864f;
                lsum += __logf(TWO_PI*v0) + __logf(TWO_PI*v1)
                      + __logf(TWO_PI*v2) + __logf(TWO_PI*v3);
            }
            lsum += __shfl_xor_sync(0xffffffffu, lsum, 1);
            qsum += __shfl_xor_sync(0xffffffffu, qsum, 1);
            if ((tid & 1) == 0) {
                // logc const: -16*sum(log(2*pi*v)) - 0.5*sum(m^2/v) + log w
                sm_c[k] = fmaf(-16.0f, lsum, fmaf(-0.5f, qsum, __logf(weights[k])));
            }
        }
        __syncthreads();

        // ---- regather full x (packed pairs) ----
        u64 x0p[ND/2], x1p[ND/2];
        {
            const ulonglong2* p0 = reinterpret_cast<const ulonglong2*>(xs0);
            const ulonglong2* p1 = reinterpret_cast<const ulonglong2*>(xs1);
            #pragma unroll
            for (int jj = 0; jj < 8; jj++) {
                ulonglong2 a = p0[jj]; x0p[2*jj] = a.x; x0p[2*jj+1] = a.y;
                ulonglong2 b = p1[jj]; x1p[2*jj] = b.x; x1p[2*jj+1] = b.y;
            }
        }

        // ---- pass 1: logc for this lane's 4 components, both samples ----
        float lc0[KPER], lc1[KPER];
        #pragma unroll 1
        for (int kk = 0; kk < KPER; kk++) {
            int k = kk * GSIZE + lane;
            const ulonglong2* tp = reinterpret_cast<const ulonglong2*>(sm_tab + k * TS4);
            u64 sA0 = 0ull, sB0 = 0ull, sA1 = 0ull, sB1 = 0ull;
            #pragma unroll
            for (int c = 0; c < 16; c += 2) {
                ulonglong2 v0 = tp[c];       // .x = ivh pair, .y = am pair
                ulonglong2 v1 = tp[c+1];
                u64 tA0 = fma2_(v0.x, x0p[c],   v0.y);
                u64 tB0 = fma2_(v1.x, x0p[c+1], v1.y);
                u64 tA1 = fma2_(v0.x, x1p[c],   v0.y);
                u64 tB1 = fma2_(v1.x, x1p[c+1], v1.y);
                sA0 = fma2_(tA0, x0p[c],   sA0);
                sB0 = fma2_(tB0, x0p[c+1], sB0);
                sA1 = fma2_(tA1, x1p[c],   sA1);
                sB1 = fma2_(tB1, x1p[c+1], sB1);
            }
            float cK = sm_c[k];
            float lo, hi;
            upk2(add2(sA0, sB0), lo, hi);  lc0[kk] = (lo + hi) + cK;
            upk2(add2(sA1, sB1), lo, hi);  lc1[kk] = (lo + hi) + cK;
        }

        // ---- max over group, weights, denominators ----
        float M0 = fmaxf(fmaxf(lc0[0], lc0[1]), fmaxf(lc0[2], lc0[3]));
        float M1 = fmaxf(fmaxf(lc1[0], lc1[1]), fmaxf(lc1[2], lc1[3]));
        #pragma unroll
        for (int r = 1; r <= 8; r <<= 1) {
            M0 = fmaxf(M0, __shfl_xor_sync(0xffffffffu, M0, r));
            M1 = fmaxf(M1, __shfl_xor_sync(0xffffffffu, M1, r));
        }
        float S0 = 0.0f, S1 = 0.0f;
        #pragma unroll
        for (int kk = 0; kk < KPER; kk++) {
            int k = kk * GSIZE + lane;
            float w0 = __expf(lc0[kk] - M0);
            float w1 = __expf(lc1[kk] - M1);
            S0 += w0; S1 += w1;
            wrow[k] = make_float4(w0, w0, w1, w1);
        }
        #pragma unroll
        for (int r = 1; r <= 8; r <<= 1) {
            S0 += __shfl_xor_sync(0xffffffffu, S0, r);
            S1 += __shfl_xor_sync(0xffffffffu, S1, r);
        }
        __syncwarp();

        // ---- pass 2: P,Q accumulation over ALL 64 k for this lane's dim pair ----
        u64 P0 = 0ull, Q0 = 0ull, P1 = 0ull, Q1 = 0ull;
        {
            const ulonglong2* wp = reinterpret_cast<const ulonglong2*>(wrow);
            #pragma unroll 4
            for (int k = 0; k < NK; k++) {
                ulonglong2 tv = *reinterpret_cast<const ulonglong2*>(sm_tab + k * TS4 + lane);
                ulonglong2 wv = wp[k];
                P0 = fma2_(wv.x, tv.x, P0);
                Q0 = fma2_(wv.x, tv.y, Q0);
                P1 = fma2_(wv.y, tv.x, P1);
                Q1 = fma2_(wv.y, tv.y, Q1);
            }
        }

        // ---- Euler-Maruyama update of this lane's 2 dims, both samples ----
        {
            float iS0 = 1.0f / S0, iS1 = 1.0f / S1;
            float2 z0 = *reinterpret_cast<const float2*>(
                noise + ((size_t)i * NB + (size_t)cs0) * ND + d0);
            float2 z1 = *reinterpret_cast<const float2*>(
                noise + ((size_t)i * NB + (size_t)cs1) * ND + d0);
            float2 xo0 = *reinterpret_cast<const float2*>(xs0 + d0);
            float2 xo1 = *reinterpret_cast<const float2*>(xs1 + d0);
            float p0a,p0b,q0a,q0b,p1a,p1b,q1a,q1b;
            upk2(P0, p0a, p0b); upk2(Q0, q0a, q0b);
            upk2(P1, p1a, p1b); upk2(Q1, q1a, q1b);
            float2 xn0, xn1;
            xn0.x = upd1(xo0.x, p0a, q0a, iS0, hb, sn, z0.x);
            xn0.y = upd1(xo0.y, p0b, q0b, iS0, hb, sn, z0.y);
            xn1.x = upd1(xo1.x, p1a, q1a, iS1, hb, sn, z1.x);
            xn1.y = upd1(xo1.y, p1b, q1b, iS1, hb, sn, z1.y);
            *reinterpret_cast<float2*>(xs0 + d0) = xn0;
            *reinterpret_cast<float2*>(xs1 + d0) = xn1;
        }
    }

    // ---- final store (each lane stores its 2 dims; coalesced 128B per sample) ----
    if (s0r < NB)
        *reinterpret_cast<float2*>(out + (size_t)s0r * ND + d0) =
            *reinterpret_cast<const float2*>(xs0 + d0);
    if (s1r < NB)
        *reinterpret_cast<float2*>(out + (size_t)s1r * ND + d0) =
            *reinterpret_cast<const float2*>(xs1 + d0);
}

extern "C" void kernel_launch(void* const* d_in, const int* in_sizes, int n_in,
                              void* d_out, int out_size)
{
    const float* x_init  = (const float*)d_in[0];
    const float* centers = (const float*)d_in[1];
    const float* stds    = (const float*)d_in[2];
    const float* weights = (const float*)d_in[3];
    const float* noise   = (const float*)d_in[4];
    float* out = (float*)d_out;

    sbm_kernel<<<NBLK, TPB>>>(x_init, centers, stds, weights, noise, out);
}